// round 1
// baseline (speedup 1.0000x reference)
#include <cuda_runtime.h>
#include <math.h>

#define BATCH   8
#define TLEN    16384
#define NPOS    (BATCH*TLEN)     // 131072
#define RC      32
#define CIN     256
#define COUT    256
#define NLAYERS 40
#define NBLK    (NPOS/256)       // 512

// Persistent scratch (no allocation allowed): ping-pong h + skip accumulator.
// Channel-major layout: [channel][position] for fully coalesced access.
__device__ float g_h[2][RC * NPOS];
__device__ float g_skip[RC * NPOS];

__device__ __forceinline__ float fsig(float x) {
    return __fdividef(1.0f, 1.0f + __expf(-x));
}
__device__ __forceinline__ float ftanh(float x) {
    // tanh(x) = 1 - 2/(e^{2x}+1); saturates correctly at +-inf
    return 1.0f - __fdividef(2.0f, __expf(2.0f * x) + 1.0f);
}

// ---------------------------------------------------------------------------
// Input 1x1 conv: h = in_w[32,256] @ x[B,256,T] + in_b   -> g_h[0] [32][NPOS]
// ---------------------------------------------------------------------------
__global__ __launch_bounds__(256) void k_input(
    const float* __restrict__ x, const float* __restrict__ w,
    const float* __restrict__ b, float* __restrict__ hout)
{
    __shared__ float ws[CIN * RC];   // transposed: [ic][o] so float4 over o
    __shared__ float bs[RC];
    int tid = threadIdx.x;
    for (int idx = tid; idx < CIN * RC; idx += 256) {
        int o = idx / CIN, ic = idx % CIN;
        ws[ic * RC + o] = w[idx];
    }
    if (tid < RC) bs[tid] = b[tid];
    __syncthreads();

    int p  = blockIdx.x * 256 + tid;
    int bb = p >> 14;            // / TLEN
    int t  = p & (TLEN - 1);
    const float* xp = x + ((size_t)bb * CIN) * TLEN + t;

    float acc[RC];
#pragma unroll
    for (int o = 0; o < RC; o++) acc[o] = bs[o];

    for (int ic = 0; ic < CIN; ic++) {
        float xv = __ldg(xp + (size_t)ic * TLEN);
        const float4* w4 = (const float4*)(ws + ic * RC);
#pragma unroll
        for (int q = 0; q < 8; q++) {
            float4 wv = w4[q];
            acc[q*4+0] = fmaf(wv.x, xv, acc[q*4+0]);
            acc[q*4+1] = fmaf(wv.y, xv, acc[q*4+1]);
            acc[q*4+2] = fmaf(wv.z, xv, acc[q*4+2]);
            acc[q*4+3] = fmaf(wv.w, xv, acc[q*4+3]);
        }
    }
#pragma unroll
    for (int o = 0; o < RC; o++) hout[(size_t)o * NPOS + p] = acc[o];
}

// ---------------------------------------------------------------------------
// One WaveNet residual layer:
//   a = tanh(dconv(h)) * sigmoid(dgate(h));  hout = h + res(a);  skip += skp(a)
// ---------------------------------------------------------------------------
__global__ __launch_bounds__(256) void k_layer(
    const float* __restrict__ hin, float* __restrict__ hout,
    float* __restrict__ skip,
    const float* __restrict__ cw, const float* __restrict__ cb,
    const float* __restrict__ gw, const float* __restrict__ gb,
    const float* __restrict__ rw, const float* __restrict__ rb,
    const float* __restrict__ sw, const float* __restrict__ sb,
    int d, int first)
{
    __shared__ float4 wq[RC * RC];   // (o,ic): {conv_k0, conv_k1, gate_k0, gate_k1}
    __shared__ float2 wrs[RC * RC];  // (o,ic): {res, skip}
    __shared__ float  bc[RC], bg[RC], br[RC], bsk[RC];

    int tid = threadIdx.x;
    for (int idx = tid; idx < RC * RC; idx += 256) {
        wq[idx]  = make_float4(cw[2*idx], cw[2*idx+1], gw[2*idx], gw[2*idx+1]);
        wrs[idx] = make_float2(rw[idx], sw[idx]);
    }
    if (tid < RC) { bc[tid]=cb[tid]; bg[tid]=gb[tid]; br[tid]=rb[tid]; bsk[tid]=sb[tid]; }
    __syncthreads();

    int p = blockIdx.x * 256 + tid;
    int t = p & (TLEN - 1);
    bool hasprev = (t >= d);
    int  pp = p - d;

    float xc[RC], xq[RC];
#pragma unroll
    for (int i = 0; i < RC; i++) {
        xc[i] = hin[(size_t)i * NPOS + p];
        xq[i] = hasprev ? hin[(size_t)i * NPOS + pp] : 0.0f;
    }

    float a[RC];
#pragma unroll
    for (int o = 0; o < RC; o++) {
        float c = bc[o], g = bg[o];
        const float4* wp = wq + o * RC;
#pragma unroll
        for (int i = 0; i < RC; i++) {
            float4 w = wp[i];
            c = fmaf(w.x, xq[i], c);
            c = fmaf(w.y, xc[i], c);
            g = fmaf(w.z, xq[i], g);
            g = fmaf(w.w, xc[i], g);
        }
        a[o] = ftanh(c) * fsig(g);
    }

#pragma unroll
    for (int o = 0; o < RC; o++) {
        float r = br[o], s = bsk[o];
        const float2* wp = wrs + o * RC;
#pragma unroll
        for (int i = 0; i < RC; i++) {
            float2 w = wp[i];
            r = fmaf(w.x, a[i], r);
            s = fmaf(w.y, a[i], s);
        }
        size_t idx = (size_t)o * NPOS + p;
        hout[idx] = xc[o] + r;
        skip[idx] = first ? s : (skip[idx] + s);
    }
}

// ---------------------------------------------------------------------------
// Output head: out = s2( relu(s1(skip)) ),  out layout [B][256][T]
// ---------------------------------------------------------------------------
__global__ __launch_bounds__(256) void k_final(
    const float* __restrict__ skip,
    const float* __restrict__ w1, const float* __restrict__ b1,
    const float* __restrict__ w2, const float* __restrict__ b2,
    float* __restrict__ out)
{
    __shared__ float ws1[RC * RC];
    __shared__ float ws2[COUT * RC];
    __shared__ float bs1[RC];
    __shared__ float bs2[COUT];
    int tid = threadIdx.x;
    for (int idx = tid; idx < RC * RC; idx += 256)   ws1[idx] = w1[idx];
    for (int idx = tid; idx < COUT * RC; idx += 256) ws2[idx] = w2[idx];
    if (tid < RC) bs1[tid] = b1[tid];
    if (tid < COUT) bs2[tid] = b2[tid];
    __syncthreads();

    int p  = blockIdx.x * 256 + tid;
    int bb = p >> 14;
    int t  = p & (TLEN - 1);

    float sk[RC];
#pragma unroll
    for (int i = 0; i < RC; i++) sk[i] = skip[(size_t)i * NPOS + p];

    float u[RC];
#pragma unroll
    for (int o = 0; o < RC; o++) {
        float acc = bs1[o];
#pragma unroll
        for (int i = 0; i < RC; i++) acc = fmaf(ws1[o * RC + i], sk[i], acc);
        u[o] = fmaxf(acc, 0.0f);
    }

    float* op = out + ((size_t)bb * COUT) * TLEN + t;
    for (int o = 0; o < COUT; o++) {
        float acc = bs2[o];
        const float4* wp = (const float4*)(ws2 + o * RC);
#pragma unroll
        for (int q = 0; q < 8; q++) {
            float4 w = wp[q];
            acc = fmaf(w.x, u[q*4+0], acc);
            acc = fmaf(w.y, u[q*4+1], acc);
            acc = fmaf(w.z, u[q*4+2], acc);
            acc = fmaf(w.w, u[q*4+3], acc);
        }
        op[(size_t)o * TLEN] = acc;
    }
}

// ---------------------------------------------------------------------------
extern "C" void kernel_launch(void* const* d_in, const int* in_sizes, int n_in,
                              void* d_out, int out_size)
{
    const float* x      = (const float*)d_in[0];
    const float* in_w   = (const float*)d_in[1];
    const float* in_b   = (const float*)d_in[2];
    const float* conv_w = (const float*)d_in[3];
    const float* conv_b = (const float*)d_in[4];
    const float* gate_w = (const float*)d_in[5];
    const float* gate_b = (const float*)d_in[6];
    const float* res_w  = (const float*)d_in[7];
    const float* res_b  = (const float*)d_in[8];
    const float* skip_w = (const float*)d_in[9];
    const float* skip_b = (const float*)d_in[10];
    const float* s1_w   = (const float*)d_in[11];
    const float* s1_b   = (const float*)d_in[12];
    const float* s2_w   = (const float*)d_in[13];
    const float* s2_b   = (const float*)d_in[14];
    float* out = (float*)d_out;

    float* hbase = nullptr;
    float* skp   = nullptr;
    cudaGetSymbolAddress((void**)&hbase, g_h);
    cudaGetSymbolAddress((void**)&skp, g_skip);

    k_input<<<NBLK, 256>>>(x, in_w, in_b, hbase);

    int cur = 0;
    for (int i = 0; i < NLAYERS; i++) {
        int dd = 1 << (i % 10);
        const float* hin = hbase + (size_t)cur * RC * NPOS;
        float* hout      = hbase + (size_t)(cur ^ 1) * RC * NPOS;
        k_layer<<<NBLK, 256>>>(hin, hout, skp,
                               conv_w + (size_t)i * RC * RC * 2, conv_b + i * RC,
                               gate_w + (size_t)i * RC * RC * 2, gate_b + i * RC,
                               res_w  + (size_t)i * RC * RC,     res_b  + i * RC,
                               skip_w + (size_t)i * RC * RC,     skip_b + i * RC,
                               dd, (i == 0) ? 1 : 0);
        cur ^= 1;
    }

    k_final<<<NBLK, 256>>>(skp, s1_w, s1_b, s2_w, s2_b, out);
}

// round 2
// speedup vs baseline: 1.0816x; 1.0816x over previous
#include <cuda_runtime.h>
#include <math.h>

#define BATCH   8
#define TLEN    16384
#define NPOS    (BATCH*TLEN)     // 131072
#define RC      32
#define CIN     256
#define COUT    256
#define NLAYERS 40
#define TILE    64               // positions per block in k_layer
#define LGRID   (NPOS/TILE)      // 2048

// Persistent scratch: ping-pong h + skip accumulator, channel-major [ch][pos].
__device__ float g_h[2][RC * NPOS];
__device__ float g_skip[RC * NPOS];

__device__ __forceinline__ float fsig(float x) {
    return __fdividef(1.0f, 1.0f + __expf(-x));
}
__device__ __forceinline__ float ftanh(float x) {
    return 1.0f - __fdividef(2.0f, __expf(2.0f * x) + 1.0f);
}

// ---------------------------------------------------------------------------
// Input 1x1 conv: h = in_w[32,256] @ x[B,256,T] + in_b  -> [32][NPOS]
// ---------------------------------------------------------------------------
__global__ __launch_bounds__(256) void k_input(
    const float* __restrict__ x, const float* __restrict__ w,
    const float* __restrict__ b, float* __restrict__ hout)
{
    __shared__ float ws[CIN * RC];   // [ic][o]
    __shared__ float bs[RC];
    int tid = threadIdx.x;
    for (int idx = tid; idx < CIN * RC; idx += 256) {
        int o = idx / CIN, ic = idx % CIN;
        ws[ic * RC + o] = w[idx];
    }
    if (tid < RC) bs[tid] = b[tid];
    __syncthreads();

    int p  = blockIdx.x * 256 + tid;
    int bb = p >> 14;
    int t  = p & (TLEN - 1);
    const float* xp = x + ((size_t)bb * CIN) * TLEN + t;

    float acc[RC];
#pragma unroll
    for (int o = 0; o < RC; o++) acc[o] = bs[o];

    for (int ic = 0; ic < CIN; ic++) {
        float xv = __ldg(xp + (size_t)ic * TLEN);
        const float4* w4 = (const float4*)(ws + ic * RC);
#pragma unroll
        for (int q = 0; q < 8; q++) {
            float4 wv = w4[q];
            acc[q*4+0] = fmaf(wv.x, xv, acc[q*4+0]);
            acc[q*4+1] = fmaf(wv.y, xv, acc[q*4+1]);
            acc[q*4+2] = fmaf(wv.z, xv, acc[q*4+2]);
            acc[q*4+3] = fmaf(wv.w, xv, acc[q*4+3]);
        }
    }
#pragma unroll
    for (int o = 0; o < RC; o++) hout[(size_t)o * NPOS + p] = acc[o];
}

// ---------------------------------------------------------------------------
// One residual layer, warp-cooperative tile GEMM.
// Block: 256 thr = 8 warps. Tile: 64 positions. Warp w -> outputs [4w,4w+4).
// Lane l -> positions {2l, 2l+1}.
// ---------------------------------------------------------------------------
__global__ __launch_bounds__(256) void k_layer(
    const float* __restrict__ hin, float* __restrict__ hout,
    float* __restrict__ skip,
    const float* __restrict__ cw, const float* __restrict__ cb,
    const float* __restrict__ gw, const float* __restrict__ gb,
    const float* __restrict__ rw, const float* __restrict__ rb,
    const float* __restrict__ sw, const float* __restrict__ sb,
    int d, int first)
{
    __shared__ float  sh_cur[RC][TILE];   // h(t) tile                  8KB
    __shared__ float  sh_pa[RC][TILE];    // h(t-d) tile, then 'a' tile 8KB
    __shared__ float4 swq[RC][RC];        // [i][o] {c_k0,c_k1,g_k0,g_k1} 16KB
    __shared__ float4 swrs[RC][RC/2];     // [i][o/2] {r0,s0,r1,s1}       8KB

    int tid  = threadIdx.x;
    int base = blockIdx.x * TILE;
    int t0   = base & (TLEN - 1);

    // Stage current tile (vectorized float2)
    for (int k = tid; k < RC * (TILE/2); k += 256) {
        int row = k >> 5, c2 = k & 31;
        ((float2*)sh_cur[row])[c2] =
            ((const float2*)(hin + (size_t)row * NPOS + base))[c2];
    }
    // Stage dilated (prev) tile with causal zero-pad
    for (int k = tid; k < RC * TILE; k += 256) {
        int row = k >> 6, j = k & 63;
        float v = 0.0f;
        if (t0 + j >= d) v = hin[(size_t)row * NPOS + base + j - d];
        sh_pa[row][j] = v;
    }
    // Stage conv+gate weights: swq[i][o] = {cw[o,i,0], cw[o,i,1], gw[o,i,0], gw[o,i,1]}
    for (int k = tid; k < RC * RC; k += 256) {
        int i = k >> 5, o = k & 31;
        int idx = o * RC + i;
        swq[i][o] = make_float4(cw[2*idx], cw[2*idx+1], gw[2*idx], gw[2*idx+1]);
    }
    // Stage res+skip weights pairs: swrs[i][p] = {rw[2p,i], sw[2p,i], rw[2p+1,i], sw[2p+1,i]}
    for (int k = tid; k < RC * (RC/2); k += 256) {
        int i = k >> 4, p2 = k & 15;
        swrs[i][p2] = make_float4(rw[(2*p2) * RC + i], sw[(2*p2) * RC + i],
                                  rw[(2*p2+1) * RC + i], sw[(2*p2+1) * RC + i]);
    }
    __syncthreads();

    int wid = tid >> 5, l = tid & 31;
    int ow0 = wid * 4;
    int j0  = l * 2;

    // ---- Phase 1: conv + gate GEMM (4 outputs x 2 positions per thread) ----
    float2 c[4], g[4];
#pragma unroll
    for (int oo = 0; oo < 4; oo++) {
        float bcv = __ldg(cb + ow0 + oo);
        float bgv = __ldg(gb + ow0 + oo);
        c[oo] = make_float2(bcv, bcv);
        g[oo] = make_float2(bgv, bgv);
    }
#pragma unroll 4
    for (int i = 0; i < RC; i++) {
        float2 xc = *(const float2*)&sh_cur[i][j0];
        float2 xp = *(const float2*)&sh_pa[i][j0];
#pragma unroll
        for (int oo = 0; oo < 4; oo++) {
            float4 W = swq[i][ow0 + oo];
            c[oo].x = fmaf(W.x, xp.x, c[oo].x);
            c[oo].x = fmaf(W.y, xc.x, c[oo].x);
            c[oo].y = fmaf(W.x, xp.y, c[oo].y);
            c[oo].y = fmaf(W.y, xc.y, c[oo].y);
            g[oo].x = fmaf(W.z, xp.x, g[oo].x);
            g[oo].x = fmaf(W.w, xc.x, g[oo].x);
            g[oo].y = fmaf(W.z, xp.y, g[oo].y);
            g[oo].y = fmaf(W.w, xc.y, g[oo].y);
        }
    }

    // ---- Gated activation ----
    float2 a[4];
#pragma unroll
    for (int oo = 0; oo < 4; oo++) {
        a[oo].x = ftanh(c[oo].x) * fsig(g[oo].x);
        a[oo].y = ftanh(c[oo].y) * fsig(g[oo].y);
    }

    // Round-trip 'a' through shared (overlay dead prev tile)
    __syncthreads();
#pragma unroll
    for (int oo = 0; oo < 4; oo++)
        *(float2*)&sh_pa[ow0 + oo][j0] = a[oo];
    __syncthreads();

    // ---- Phase 2: res + skip GEMM ----
    float2 r[4], s[4];
#pragma unroll
    for (int oo = 0; oo < 4; oo++) {
        float brv = __ldg(rb + ow0 + oo);
        float bsv = __ldg(sb + ow0 + oo);
        r[oo] = make_float2(brv, brv);
        s[oo] = make_float2(bsv, bsv);
    }
#pragma unroll 4
    for (int i = 0; i < RC; i++) {
        float2 av = *(const float2*)&sh_pa[i][j0];
#pragma unroll
        for (int pp = 0; pp < 2; pp++) {
            float4 W = swrs[i][(ow0 >> 1) + pp];
            r[2*pp  ].x = fmaf(W.x, av.x, r[2*pp  ].x);
            r[2*pp  ].y = fmaf(W.x, av.y, r[2*pp  ].y);
            s[2*pp  ].x = fmaf(W.y, av.x, s[2*pp  ].x);
            s[2*pp  ].y = fmaf(W.y, av.y, s[2*pp  ].y);
            r[2*pp+1].x = fmaf(W.z, av.x, r[2*pp+1].x);
            r[2*pp+1].y = fmaf(W.z, av.y, r[2*pp+1].y);
            s[2*pp+1].x = fmaf(W.w, av.x, s[2*pp+1].x);
            s[2*pp+1].y = fmaf(W.w, av.y, s[2*pp+1].y);
        }
    }

    // ---- Writeback: hout = h + res, skip (+)= s ----
#pragma unroll
    for (int oo = 0; oo < 4; oo++) {
        size_t idx = (size_t)(ow0 + oo) * NPOS + base + j0;
        float2 xc = *(const float2*)&sh_cur[ow0 + oo][j0];
        float2 ho = make_float2(xc.x + r[oo].x, xc.y + r[oo].y);
        *(float2*)&hout[idx] = ho;
        float2 sv = s[oo];
        if (!first) {
            float2 old = *(const float2*)&skip[idx];
            sv.x += old.x; sv.y += old.y;
        }
        *(float2*)&skip[idx] = sv;
    }
}

// ---------------------------------------------------------------------------
// Output head: out = s2( relu(s1(skip)) ), out layout [B][256][T]
// ---------------------------------------------------------------------------
__global__ __launch_bounds__(256) void k_final(
    const float* __restrict__ skip,
    const float* __restrict__ w1, const float* __restrict__ b1,
    const float* __restrict__ w2, const float* __restrict__ b2,
    float* __restrict__ out)
{
    __shared__ float ws1[RC * RC];
    __shared__ float ws2[COUT * RC];
    __shared__ float bs1[RC];
    __shared__ float bs2[COUT];
    int tid = threadIdx.x;
    for (int idx = tid; idx < RC * RC; idx += 256)   ws1[idx] = w1[idx];
    for (int idx = tid; idx < COUT * RC; idx += 256) ws2[idx] = w2[idx];
    if (tid < RC) bs1[tid] = b1[tid];
    if (tid < COUT) bs2[tid] = b2[tid];
    __syncthreads();

    int p  = blockIdx.x * 256 + tid;
    int bb = p >> 14;
    int t  = p & (TLEN - 1);

    float sk[RC];
#pragma unroll
    for (int i = 0; i < RC; i++) sk[i] = skip[(size_t)i * NPOS + p];

    float u[RC];
#pragma unroll
    for (int o = 0; o < RC; o++) {
        float acc = bs1[o];
#pragma unroll
        for (int i = 0; i < RC; i++) acc = fmaf(ws1[o * RC + i], sk[i], acc);
        u[o] = fmaxf(acc, 0.0f);
    }

    float* op = out + ((size_t)bb * COUT) * TLEN + t;
    for (int o = 0; o < COUT; o++) {
        float acc = bs2[o];
        const float4* wp = (const float4*)(ws2 + o * RC);
#pragma unroll
        for (int q = 0; q < 8; q++) {
            float4 w = wp[q];
            acc = fmaf(w.x, u[q*4+0], acc);
            acc = fmaf(w.y, u[q*4+1], acc);
            acc = fmaf(w.z, u[q*4+2], acc);
            acc = fmaf(w.w, u[q*4+3], acc);
        }
        op[(size_t)o * TLEN] = acc;
    }
}

// ---------------------------------------------------------------------------
extern "C" void kernel_launch(void* const* d_in, const int* in_sizes, int n_in,
                              void* d_out, int out_size)
{
    const float* x      = (const float*)d_in[0];
    const float* in_w   = (const float*)d_in[1];
    const float* in_b   = (const float*)d_in[2];
    const float* conv_w = (const float*)d_in[3];
    const float* conv_b = (const float*)d_in[4];
    const float* gate_w = (const float*)d_in[5];
    const float* gate_b = (const float*)d_in[6];
    const float* res_w  = (const float*)d_in[7];
    const float* res_b  = (const float*)d_in[8];
    const float* skip_w = (const float*)d_in[9];
    const float* skip_b = (const float*)d_in[10];
    const float* s1_w   = (const float*)d_in[11];
    const float* s1_b   = (const float*)d_in[12];
    const float* s2_w   = (const float*)d_in[13];
    const float* s2_b   = (const float*)d_in[14];
    float* out = (float*)d_out;

    float* hbase = nullptr;
    float* skp   = nullptr;
    cudaGetSymbolAddress((void**)&hbase, g_h);
    cudaGetSymbolAddress((void**)&skp, g_skip);

    k_input<<<NPOS/256, 256>>>(x, in_w, in_b, hbase);

    int cur = 0;
    for (int i = 0; i < NLAYERS; i++) {
        int dd = 1 << (i % 10);
        const float* hin = hbase + (size_t)cur * RC * NPOS;
        float* hout      = hbase + (size_t)(cur ^ 1) * RC * NPOS;
        k_layer<<<LGRID, 256>>>(hin, hout, skp,
                                conv_w + (size_t)i * RC * RC * 2, conv_b + i * RC,
                                gate_w + (size_t)i * RC * RC * 2, gate_b + i * RC,
                                res_w  + (size_t)i * RC * RC,     res_b  + i * RC,
                                skip_w + (size_t)i * RC * RC,     skip_b + i * RC,
                                dd, (i == 0) ? 1 : 0);
        cur ^= 1;
    }

    k_final<<<NPOS/256, 256>>>(skp, s1_w, s1_b, s2_w, s2_b, out);
}

// round 3
// speedup vs baseline: 1.5036x; 1.3901x over previous
#include <cuda_runtime.h>
#include <math.h>

#define BATCH   8
#define TLEN    16384
#define NPOS    (BATCH*TLEN)     // 131072
#define RC      32
#define CIN     256
#define COUT    256
#define NLAYERS 40
#define TILE    128              // positions per block in k_layer
#define LGRID   (NPOS/TILE)      // 1024

// Persistent scratch: ping-pong h + skip accumulator, channel-major [ch][pos].
__device__ float g_h[2][RC * NPOS];
__device__ float g_skip[RC * NPOS];

__device__ __forceinline__ float fsig(float x) {
    return __fdividef(1.0f, 1.0f + __expf(-x));
}
__device__ __forceinline__ float ftanh(float x) {
    return 1.0f - __fdividef(2.0f, __expf(2.0f * x) + 1.0f);
}

// ---------------------------------------------------------------------------
// Input 1x1 conv: h = in_w[32,256] @ x[B,256,T] + in_b  -> [32][NPOS]
// ---------------------------------------------------------------------------
__global__ __launch_bounds__(256) void k_input(
    const float* __restrict__ x, const float* __restrict__ w,
    const float* __restrict__ b, float* __restrict__ hout)
{
    __shared__ float ws[CIN * RC];   // [ic][o]
    __shared__ float bs[RC];
    int tid = threadIdx.x;
    for (int idx = tid; idx < CIN * RC; idx += 256) {
        int o = idx / CIN, ic = idx % CIN;
        ws[ic * RC + o] = w[idx];
    }
    if (tid < RC) bs[tid] = b[tid];
    __syncthreads();

    int p  = blockIdx.x * 256 + tid;
    int bb = p >> 14;
    int t  = p & (TLEN - 1);
    const float* xp = x + ((size_t)bb * CIN) * TLEN + t;

    float acc[RC];
#pragma unroll
    for (int o = 0; o < RC; o++) acc[o] = bs[o];

    for (int ic = 0; ic < CIN; ic++) {
        float xv = __ldg(xp + (size_t)ic * TLEN);
        const float4* w4 = (const float4*)(ws + ic * RC);
#pragma unroll
        for (int q = 0; q < 8; q++) {
            float4 wv = w4[q];
            acc[q*4+0] = fmaf(wv.x, xv, acc[q*4+0]);
            acc[q*4+1] = fmaf(wv.y, xv, acc[q*4+1]);
            acc[q*4+2] = fmaf(wv.z, xv, acc[q*4+2]);
            acc[q*4+3] = fmaf(wv.w, xv, acc[q*4+3]);
        }
    }
#pragma unroll
    for (int o = 0; o < RC; o++) hout[(size_t)o * NPOS + p] = acc[o];
}

// ---------------------------------------------------------------------------
// One residual layer. Block: 256 thr = 8 warps, tile = 128 positions.
// Warp w -> output channels [4w, 4w+4). Lane l -> positions [4l, 4l+4).
// Each thread: 4 outputs x 4 positions.
// ---------------------------------------------------------------------------
__global__ __launch_bounds__(256) void k_layer(
    const float* __restrict__ hin, float* __restrict__ hout,
    float* __restrict__ skip,
    const float* __restrict__ cw, const float* __restrict__ cb,
    const float* __restrict__ gw, const float* __restrict__ gb,
    const float* __restrict__ rw, const float* __restrict__ rb,
    const float* __restrict__ sw, const float* __restrict__ sb,
    int d, int first)
{
    __shared__ float  sh_cur[RC][TILE];   // h(t) tile                   16KB
    __shared__ float  sh_pa[RC][TILE];    // h(t-d) tile, then 'a' tile  16KB
    __shared__ float4 swq[RC][RC];        // [i][o] {c0,c1,g0,g1}        16KB
    __shared__ float4 swrs[RC][RC/2];     // [i][o/2] {r0,s0,r1,s1}       8KB

    int tid  = threadIdx.x;
    int base = blockIdx.x * TILE;
    int t0   = base & (TLEN - 1);

    // Stage current tile (float4)
    for (int k = tid; k < RC * (TILE/4); k += 256) {
        int row = k >> 5, c4 = k & 31;
        ((float4*)sh_cur[row])[c4] =
            ((const float4*)(hin + (size_t)row * NPOS + base))[c4];
    }
    // Stage dilated (prev) tile with causal zero-pad
    if (d >= 4) {
        // d, t0, j all multiples of 4: predicate is uniform per float4
        for (int k = tid; k < RC * (TILE/4); k += 256) {
            int row = k >> 5, c4 = k & 31;
            int j = c4 * 4;
            float4 v = make_float4(0.f, 0.f, 0.f, 0.f);
            if (t0 + j >= d)
                v = *(const float4*)(hin + (size_t)row * NPOS + base + j - d);
            ((float4*)sh_pa[row])[c4] = v;
        }
    } else {
        for (int k = tid; k < RC * TILE; k += 256) {
            int row = k >> 7, j = k & 127;
            float v = 0.0f;
            if (t0 + j >= d) v = hin[(size_t)row * NPOS + base + j - d];
            sh_pa[row][j] = v;
        }
    }
    // Stage conv+gate weights: swq[i][o] = {cw[o,i,0], cw[o,i,1], gw[o,i,0], gw[o,i,1]}
    for (int k = tid; k < RC * RC; k += 256) {
        int i = k >> 5, o = k & 31;
        int idx = o * RC + i;
        swq[i][o] = make_float4(cw[2*idx], cw[2*idx+1], gw[2*idx], gw[2*idx+1]);
    }
    // Stage res+skip weight pairs: swrs[i][p] = {rw[2p,i], sw[2p,i], rw[2p+1,i], sw[2p+1,i]}
    for (int k = tid; k < RC * (RC/2); k += 256) {
        int i = k >> 4, p2 = k & 15;
        swrs[i][p2] = make_float4(rw[(2*p2) * RC + i], sw[(2*p2) * RC + i],
                                  rw[(2*p2+1) * RC + i], sw[(2*p2+1) * RC + i]);
    }
    __syncthreads();

    int wid = tid >> 5, l = tid & 31;
    int ow0 = wid * 4;
    int j0  = l * 4;

    // ---- Phase 1: conv + gate GEMM (4 outputs x 4 positions) ----
    float4 c[4], g[4];
#pragma unroll
    for (int oo = 0; oo < 4; oo++) {
        float bcv = __ldg(cb + ow0 + oo);
        float bgv = __ldg(gb + ow0 + oo);
        c[oo] = make_float4(bcv, bcv, bcv, bcv);
        g[oo] = make_float4(bgv, bgv, bgv, bgv);
    }
#pragma unroll 4
    for (int i = 0; i < RC; i++) {
        float4 xc = *(const float4*)&sh_cur[i][j0];
        float4 xp = *(const float4*)&sh_pa[i][j0];
#pragma unroll
        for (int oo = 0; oo < 4; oo++) {
            float4 W = swq[i][ow0 + oo];
            c[oo].x = fmaf(W.x, xp.x, c[oo].x); c[oo].x = fmaf(W.y, xc.x, c[oo].x);
            c[oo].y = fmaf(W.x, xp.y, c[oo].y); c[oo].y = fmaf(W.y, xc.y, c[oo].y);
            c[oo].z = fmaf(W.x, xp.z, c[oo].z); c[oo].z = fmaf(W.y, xc.z, c[oo].z);
            c[oo].w = fmaf(W.x, xp.w, c[oo].w); c[oo].w = fmaf(W.y, xc.w, c[oo].w);
            g[oo].x = fmaf(W.z, xp.x, g[oo].x); g[oo].x = fmaf(W.w, xc.x, g[oo].x);
            g[oo].y = fmaf(W.z, xp.y, g[oo].y); g[oo].y = fmaf(W.w, xc.y, g[oo].y);
            g[oo].z = fmaf(W.z, xp.z, g[oo].z); g[oo].z = fmaf(W.w, xc.z, g[oo].z);
            g[oo].w = fmaf(W.z, xp.w, g[oo].w); g[oo].w = fmaf(W.w, xc.w, g[oo].w);
        }
    }

    // ---- Gated activation ----
    float4 a[4];
#pragma unroll
    for (int oo = 0; oo < 4; oo++) {
        a[oo].x = ftanh(c[oo].x) * fsig(g[oo].x);
        a[oo].y = ftanh(c[oo].y) * fsig(g[oo].y);
        a[oo].z = ftanh(c[oo].z) * fsig(g[oo].z);
        a[oo].w = ftanh(c[oo].w) * fsig(g[oo].w);
    }

    // Round-trip 'a' through shared (overlay dead prev tile)
    __syncthreads();
#pragma unroll
    for (int oo = 0; oo < 4; oo++)
        *(float4*)&sh_pa[ow0 + oo][j0] = a[oo];
    __syncthreads();

    // ---- Phase 2: res + skip GEMM ----
    float4 r[4], s[4];
#pragma unroll
    for (int oo = 0; oo < 4; oo++) {
        float brv = __ldg(rb + ow0 + oo);
        float bsv = __ldg(sb + ow0 + oo);
        r[oo] = make_float4(brv, brv, brv, brv);
        s[oo] = make_float4(bsv, bsv, bsv, bsv);
    }
#pragma unroll 4
    for (int i = 0; i < RC; i++) {
        float4 av = *(const float4*)&sh_pa[i][j0];
#pragma unroll
        for (int pp = 0; pp < 2; pp++) {
            float4 W = swrs[i][(ow0 >> 1) + pp];
            r[2*pp  ].x = fmaf(W.x, av.x, r[2*pp  ].x);
            r[2*pp  ].y = fmaf(W.x, av.y, r[2*pp  ].y);
            r[2*pp  ].z = fmaf(W.x, av.z, r[2*pp  ].z);
            r[2*pp  ].w = fmaf(W.x, av.w, r[2*pp  ].w);
            s[2*pp  ].x = fmaf(W.y, av.x, s[2*pp  ].x);
            s[2*pp  ].y = fmaf(W.y, av.y, s[2*pp  ].y);
            s[2*pp  ].z = fmaf(W.y, av.z, s[2*pp  ].z);
            s[2*pp  ].w = fmaf(W.y, av.w, s[2*pp  ].w);
            r[2*pp+1].x = fmaf(W.z, av.x, r[2*pp+1].x);
            r[2*pp+1].y = fmaf(W.z, av.y, r[2*pp+1].y);
            r[2*pp+1].z = fmaf(W.z, av.z, r[2*pp+1].z);
            r[2*pp+1].w = fmaf(W.z, av.w, r[2*pp+1].w);
            s[2*pp+1].x = fmaf(W.w, av.x, s[2*pp+1].x);
            s[2*pp+1].y = fmaf(W.w, av.y, s[2*pp+1].y);
            s[2*pp+1].z = fmaf(W.w, av.z, s[2*pp+1].z);
            s[2*pp+1].w = fmaf(W.w, av.w, s[2*pp+1].w);
        }
    }

    // ---- Writeback: hout = h + res, skip (+)= s ----
#pragma unroll
    for (int oo = 0; oo < 4; oo++) {
        size_t idx = (size_t)(ow0 + oo) * NPOS + base + j0;
        float4 xc = *(const float4*)&sh_cur[ow0 + oo][j0];
        float4 ho = make_float4(xc.x + r[oo].x, xc.y + r[oo].y,
                                xc.z + r[oo].z, xc.w + r[oo].w);
        *(float4*)&hout[idx] = ho;
        float4 sv = s[oo];
        if (!first) {
            float4 old = *(const float4*)&skip[idx];
            sv.x += old.x; sv.y += old.y; sv.z += old.z; sv.w += old.w;
        }
        *(float4*)&skip[idx] = sv;
    }
}

// ---------------------------------------------------------------------------
// Output head: out = s2( relu(s1(skip)) ), out layout [B][256][T]
// ---------------------------------------------------------------------------
__global__ __launch_bounds__(256) void k_final(
    const float* __restrict__ skip,
    const float* __restrict__ w1, const float* __restrict__ b1,
    const float* __restrict__ w2, const float* __restrict__ b2,
    float* __restrict__ out)
{
    __shared__ float ws1[RC * RC];
    __shared__ float ws2[COUT * RC];
    __shared__ float bs1[RC];
    __shared__ float bs2[COUT];
    int tid = threadIdx.x;
    for (int idx = tid; idx < RC * RC; idx += 256)   ws1[idx] = w1[idx];
    for (int idx = tid; idx < COUT * RC; idx += 256) ws2[idx] = w2[idx];
    if (tid < RC) bs1[tid] = b1[tid];
    if (tid < COUT) bs2[tid] = b2[tid];
    __syncthreads();

    int p  = blockIdx.x * 256 + tid;
    int bb = p >> 14;
    int t  = p & (TLEN - 1);

    float sk[RC];
#pragma unroll
    for (int i = 0; i < RC; i++) sk[i] = skip[(size_t)i * NPOS + p];

    float u[RC];
#pragma unroll
    for (int o = 0; o < RC; o++) {
        float acc = bs1[o];
#pragma unroll
        for (int i = 0; i < RC; i++) acc = fmaf(ws1[o * RC + i], sk[i], acc);
        u[o] = fmaxf(acc, 0.0f);
    }

    float* op = out + ((size_t)bb * COUT) * TLEN + t;
    for (int o = 0; o < COUT; o++) {
        float acc = bs2[o];
        const float4* wp = (const float4*)(ws2 + o * RC);
#pragma unroll
        for (int q = 0; q < 8; q++) {
            float4 w = wp[q];
            acc = fmaf(w.x, u[q*4+0], acc);
            acc = fmaf(w.y, u[q*4+1], acc);
            acc = fmaf(w.z, u[q*4+2], acc);
            acc = fmaf(w.w, u[q*4+3], acc);
        }
        op[(size_t)o * TLEN] = acc;
    }
}

// ---------------------------------------------------------------------------
extern "C" void kernel_launch(void* const* d_in, const int* in_sizes, int n_in,
                              void* d_out, int out_size)
{
    const float* x      = (const float*)d_in[0];
    const float* in_w   = (const float*)d_in[1];
    const float* in_b   = (const float*)d_in[2];
    const float* conv_w = (const float*)d_in[3];
    const float* conv_b = (const float*)d_in[4];
    const float* gate_w = (const float*)d_in[5];
    const float* gate_b = (const float*)d_in[6];
    const float* res_w  = (const float*)d_in[7];
    const float* res_b  = (const float*)d_in[8];
    const float* skip_w = (const float*)d_in[9];
    const float* skip_b = (const float*)d_in[10];
    const float* s1_w   = (const float*)d_in[11];
    const float* s1_b   = (const float*)d_in[12];
    const float* s2_w   = (const float*)d_in[13];
    const float* s2_b   = (const float*)d_in[14];
    float* out = (float*)d_out;

    float* hbase = nullptr;
    float* skp   = nullptr;
    cudaGetSymbolAddress((void**)&hbase, g_h);
    cudaGetSymbolAddress((void**)&skp, g_skip);

    k_input<<<NPOS/256, 256>>>(x, in_w, in_b, hbase);

    int cur = 0;
    for (int i = 0; i < NLAYERS; i++) {
        int dd = 1 << (i % 10);
        const float* hin = hbase + (size_t)cur * RC * NPOS;
        float* hout      = hbase + (size_t)(cur ^ 1) * RC * NPOS;
        k_layer<<<LGRID, 256>>>(hin, hout, skp,
                                conv_w + (size_t)i * RC * RC * 2, conv_b + i * RC,
                                gate_w + (size_t)i * RC * RC * 2, gate_b + i * RC,
                                res_w  + (size_t)i * RC * RC,     res_b  + i * RC,
                                skip_w + (size_t)i * RC * RC,     skip_b + i * RC,
                                dd, (i == 0) ? 1 : 0);
        cur ^= 1;
    }

    k_final<<<NPOS/256, 256>>>(skp, s1_w, s1_b, s2_w, s2_b, out);
}

// round 4
// speedup vs baseline: 1.5233x; 1.0131x over previous
#include <cuda_runtime.h>
#include <math.h>

#define BATCH   8
#define TLEN    16384
#define NPOS    (BATCH*TLEN)     // 131072
#define RC      32
#define CIN     256
#define COUT    256
#define NLAYERS 40
#define TILE    128
#define LGRID   (NPOS/TILE)      // 1024

typedef unsigned long long u64;

__device__ float g_h[2][RC * NPOS];
__device__ float g_skip[RC * NPOS];

__device__ __forceinline__ u64 pack2(float lo, float hi) {
    u64 r; asm("mov.b64 %0, {%1, %2};" : "=l"(r) : "f"(lo), "f"(hi)); return r;
}
__device__ __forceinline__ u64 dup2(float x) {
    u64 r; asm("mov.b64 %0, {%1, %1};" : "=l"(r) : "f"(x)); return r;
}
__device__ __forceinline__ void unpack2(u64 v, float& lo, float& hi) {
    asm("mov.b64 {%0, %1}, %2;" : "=f"(lo), "=f"(hi) : "l"(v));
}
// d = a * b + d, elementwise on packed f32x2 (exact IEEE fp32 per lane)
#define FFMA2(d, a, b) asm("fma.rn.f32x2 %0, %1, %2, %0;" : "+l"(d) : "l"(a), "l"(b))

__device__ __forceinline__ float fsig(float x) {
    return __fdividef(1.0f, 1.0f + __expf(-x));
}
__device__ __forceinline__ float ftanh(float x) {
    return 1.0f - __fdividef(2.0f, __expf(2.0f * x) + 1.0f);
}

// ---------------------------------------------------------------------------
// Input 1x1 conv: h = in_w[32,256] @ x + in_b -> [32][NPOS]
// ---------------------------------------------------------------------------
__global__ __launch_bounds__(256) void k_input(
    const float* __restrict__ x, const float* __restrict__ w,
    const float* __restrict__ b, float* __restrict__ hout)
{
    __shared__ float ws[CIN][RC];   // [ic][o]
    __shared__ float bs[RC];
    int tid = threadIdx.x;
    for (int idx = tid; idx < CIN * RC; idx += 256) {
        int o = idx / CIN, ic = idx % CIN;
        ws[ic][o] = w[idx];
    }
    if (tid < RC) bs[tid] = b[tid];
    __syncthreads();

    int p  = blockIdx.x * 256 + tid;
    int bb = p >> 14;
    int t  = p & (TLEN - 1);
    const float* xp = x + ((size_t)bb * CIN) * TLEN + t;

    u64 acc[16];  // pairs over outputs (2q, 2q+1)
#pragma unroll
    for (int q = 0; q < 16; q++) acc[q] = pack2(bs[2*q], bs[2*q+1]);

#pragma unroll 4
    for (int ic = 0; ic < CIN; ic++) {
        float xv = __ldg(xp + (size_t)ic * TLEN);
        u64 xd = dup2(xv);
        const ulonglong2* wp = (const ulonglong2*)ws[ic];
#pragma unroll
        for (int q = 0; q < 8; q++) {
            ulonglong2 wv = wp[q];
            FFMA2(acc[2*q],   wv.x, xd);
            FFMA2(acc[2*q+1], wv.y, xd);
        }
    }
#pragma unroll
    for (int q = 0; q < 16; q++) {
        float v0, v1;
        unpack2(acc[q], v0, v1);
        hout[(size_t)(2*q)   * NPOS + p] = v0;
        hout[(size_t)(2*q+1) * NPOS + p] = v1;
    }
}

// ---------------------------------------------------------------------------
// One residual layer, FFMA2 version.
// 256 thr = 8 warps, tile = 128 pos. Warp w -> out chans [4w,4w+4).
// Lane l -> positions [4l,4l+4). Accumulator pairs over adjacent outputs.
// ---------------------------------------------------------------------------
__global__ __launch_bounds__(256, 3) void k_layer(
    const float* __restrict__ hin, float* __restrict__ hout,
    float* __restrict__ skip,
    const float* __restrict__ cw, const float* __restrict__ cb,
    const float* __restrict__ gw, const float* __restrict__ gb,
    const float* __restrict__ rw, const float* __restrict__ rb,
    const float* __restrict__ sw, const float* __restrict__ sb,
    int d, int first)
{
    __shared__ float  sh_cur[RC][TILE];   // 16KB
    __shared__ float  sh_pa[RC][TILE];    // 16KB (prev tile, then 'a' tile)
    __shared__ float  swq2[RC][4][RC];    // 16KB [i][kind][o]; kind 0=ck0 1=ck1 2=gk0 3=gk1
    __shared__ float2 swrs2[RC][RC];      //  8KB [i][o] = {rw, sw}

    int tid  = threadIdx.x;
    int base = blockIdx.x * TILE;
    int t0   = base & (TLEN - 1);

    for (int k = tid; k < RC * (TILE/4); k += 256) {
        int row = k >> 5, c4 = k & 31;
        ((float4*)sh_cur[row])[c4] =
            ((const float4*)(hin + (size_t)row * NPOS + base))[c4];
    }
    if (d >= 4) {
        for (int k = tid; k < RC * (TILE/4); k += 256) {
            int row = k >> 5, c4 = k & 31;
            int j = c4 * 4;
            float4 v = make_float4(0.f, 0.f, 0.f, 0.f);
            if (t0 + j >= d)
                v = *(const float4*)(hin + (size_t)row * NPOS + base + j - d);
            ((float4*)sh_pa[row])[c4] = v;
        }
    } else {
        for (int k = tid; k < RC * TILE; k += 256) {
            int row = k >> 7, j = k & 127;
            float v = 0.0f;
            if (t0 + j >= d) v = hin[(size_t)row * NPOS + base + j - d];
            sh_pa[row][j] = v;
        }
    }
    for (int k = tid; k < RC * RC; k += 256) {
        int i = k >> 5, o = k & 31;
        int idx = o * RC + i;
        swq2[i][0][o] = cw[2*idx];
        swq2[i][1][o] = cw[2*idx+1];
        swq2[i][2][o] = gw[2*idx];
        swq2[i][3][o] = gw[2*idx+1];
        swrs2[i][o] = make_float2(rw[idx], sw[idx]);
    }
    __syncthreads();

    int wid = tid >> 5, l = tid & 31;
    int ow0 = wid * 4;
    int j0  = l * 4;

    // ---- Phase 1: conv + gate (pairs over outputs: c01=(o0,o1), c23=(o2,o3)) ----
    u64 c01[4], c23[4], g01[4], g23[4];  // [pos]
    {
        float4 cbv = *(const float4*)(cb + ow0);
        float4 gbv = *(const float4*)(gb + ow0);
        u64 cA = pack2(cbv.x, cbv.y), cB = pack2(cbv.z, cbv.w);
        u64 gA = pack2(gbv.x, gbv.y), gB = pack2(gbv.z, gbv.w);
#pragma unroll
        for (int p = 0; p < 4; p++) { c01[p]=cA; c23[p]=cB; g01[p]=gA; g23[p]=gB; }
    }

#pragma unroll 4
    for (int i = 0; i < RC; i++) {
        float4 xc4 = *(const float4*)&sh_cur[i][j0];
        float4 xp4 = *(const float4*)&sh_pa[i][j0];
        u64 xpd[4] = { dup2(xp4.x), dup2(xp4.y), dup2(xp4.z), dup2(xp4.w) };
        u64 xcd[4] = { dup2(xc4.x), dup2(xc4.y), dup2(xc4.z), dup2(xc4.w) };
        ulonglong2 wc0 = *(const ulonglong2*)&swq2[i][0][ow0];
        ulonglong2 wc1 = *(const ulonglong2*)&swq2[i][1][ow0];
        ulonglong2 wg0 = *(const ulonglong2*)&swq2[i][2][ow0];
        ulonglong2 wg1 = *(const ulonglong2*)&swq2[i][3][ow0];
#pragma unroll
        for (int p = 0; p < 4; p++) {
            FFMA2(c01[p], wc0.x, xpd[p]);
            FFMA2(c01[p], wc1.x, xcd[p]);
            FFMA2(c23[p], wc0.y, xpd[p]);
            FFMA2(c23[p], wc1.y, xcd[p]);
            FFMA2(g01[p], wg0.x, xpd[p]);
            FFMA2(g01[p], wg1.x, xcd[p]);
            FFMA2(g23[p], wg0.y, xpd[p]);
            FFMA2(g23[p], wg1.y, xcd[p]);
        }
    }

    // ---- Gated activation ----
    float av[4][4];  // [oo][p]
#pragma unroll
    for (int p = 0; p < 4; p++) {
        float c0,c1,c2,c3,g0,g1,g2,g3;
        unpack2(c01[p], c0, c1); unpack2(c23[p], c2, c3);
        unpack2(g01[p], g0, g1); unpack2(g23[p], g2, g3);
        av[0][p] = ftanh(c0) * fsig(g0);
        av[1][p] = ftanh(c1) * fsig(g1);
        av[2][p] = ftanh(c2) * fsig(g2);
        av[3][p] = ftanh(c3) * fsig(g3);
    }

    __syncthreads();
#pragma unroll
    for (int oo = 0; oo < 4; oo++)
        *(float4*)&sh_pa[ow0 + oo][j0] =
            make_float4(av[oo][0], av[oo][1], av[oo][2], av[oo][3]);
    __syncthreads();

    // ---- Phase 2: res + skip (pairs = (res, skip) per output) ----
    u64 rs[4][4];  // [oo][pos]
    {
        float4 rbv = *(const float4*)(rb + ow0);
        float4 sbv = *(const float4*)(sb + ow0);
        u64 b0 = pack2(rbv.x, sbv.x), b1 = pack2(rbv.y, sbv.y);
        u64 b2 = pack2(rbv.z, sbv.z), b3 = pack2(rbv.w, sbv.w);
#pragma unroll
        for (int p = 0; p < 4; p++) { rs[0][p]=b0; rs[1][p]=b1; rs[2][p]=b2; rs[3][p]=b3; }
    }

#pragma unroll 4
    for (int i = 0; i < RC; i++) {
        float4 a4 = *(const float4*)&sh_pa[i][j0];
        u64 ad[4] = { dup2(a4.x), dup2(a4.y), dup2(a4.z), dup2(a4.w) };
        ulonglong2 w01 = *(const ulonglong2*)&swrs2[i][ow0];
        ulonglong2 w23 = *(const ulonglong2*)&swrs2[i][ow0 + 2];
#pragma unroll
        for (int p = 0; p < 4; p++) {
            FFMA2(rs[0][p], w01.x, ad[p]);
            FFMA2(rs[1][p], w01.y, ad[p]);
            FFMA2(rs[2][p], w23.x, ad[p]);
            FFMA2(rs[3][p], w23.y, ad[p]);
        }
    }

    // ---- Writeback ----
#pragma unroll
    for (int oo = 0; oo < 4; oo++) {
        size_t idx = (size_t)(ow0 + oo) * NPOS + base + j0;
        float4 xc = *(const float4*)&sh_cur[ow0 + oo][j0];
        float rv0,sv0,rv1,sv1,rv2,sv2,rv3,sv3;
        unpack2(rs[oo][0], rv0, sv0);
        unpack2(rs[oo][1], rv1, sv1);
        unpack2(rs[oo][2], rv2, sv2);
        unpack2(rs[oo][3], rv3, sv3);
        float4 ho = make_float4(xc.x + rv0, xc.y + rv1, xc.z + rv2, xc.w + rv3);
        *(float4*)&hout[idx] = ho;
        float4 sv = make_float4(sv0, sv1, sv2, sv3);
        if (!first) {
            float4 old = *(const float4*)&skip[idx];
            sv.x += old.x; sv.y += old.y; sv.z += old.z; sv.w += old.w;
        }
        *(float4*)&skip[idx] = sv;
    }
}

// ---------------------------------------------------------------------------
// Output head: out = s2( relu(s1(skip)) )
// ---------------------------------------------------------------------------
__global__ __launch_bounds__(256) void k_final(
    const float* __restrict__ skip,
    const float* __restrict__ w1, const float* __restrict__ b1,
    const float* __restrict__ w2, const float* __restrict__ b2,
    float* __restrict__ out)
{
    __shared__ float ws1[RC * RC];
    __shared__ float ws2t[RC][COUT];   // transposed [i][o], 32KB
    __shared__ float bs1[RC];
    __shared__ float bs2[COUT];
    int tid = threadIdx.x;
    for (int idx = tid; idx < RC * RC; idx += 256) ws1[idx] = w1[idx];
    for (int idx = tid; idx < COUT * RC; idx += 256) {
        int o = idx / RC, i = idx % RC;
        ws2t[i][o] = w2[idx];
    }
    if (tid < RC) bs1[tid] = b1[tid];
    if (tid < COUT) bs2[tid] = b2[tid];
    __syncthreads();

    int p  = blockIdx.x * 256 + tid;
    int bb = p >> 14;
    int t  = p & (TLEN - 1);

    float sk[RC];
#pragma unroll
    for (int i = 0; i < RC; i++) sk[i] = skip[(size_t)i * NPOS + p];

    float u[RC];
#pragma unroll
    for (int o = 0; o < RC; o++) {
        float acc = bs1[o];
#pragma unroll
        for (int i = 0; i < RC; i++) acc = fmaf(ws1[o * RC + i], sk[i], acc);
        u[o] = fmaxf(acc, 0.0f);
    }

    float* op = out + ((size_t)bb * COUT) * TLEN + t;
    for (int og = 0; og < COUT / 16; og++) {
        int o0 = og * 16;
        u64 acc[8];
#pragma unroll
        for (int q = 0; q < 8; q++) acc[q] = pack2(bs2[o0 + 2*q], bs2[o0 + 2*q + 1]);
#pragma unroll 8
        for (int i = 0; i < RC; i++) {
            u64 ud = dup2(u[i]);
            const ulonglong2* wp = (const ulonglong2*)&ws2t[i][o0];
#pragma unroll
            for (int q2 = 0; q2 < 4; q2++) {
                ulonglong2 wv = wp[q2];
                FFMA2(acc[2*q2],   wv.x, ud);
                FFMA2(acc[2*q2+1], wv.y, ud);
            }
        }
#pragma unroll
        for (int q = 0; q < 8; q++) {
            float v0, v1;
            unpack2(acc[q], v0, v1);
            op[(size_t)(o0 + 2*q)     * TLEN] = v0;
            op[(size_t)(o0 + 2*q + 1) * TLEN] = v1;
        }
    }
}

// ---------------------------------------------------------------------------
extern "C" void kernel_launch(void* const* d_in, const int* in_sizes, int n_in,
                              void* d_out, int out_size)
{
    const float* x      = (const float*)d_in[0];
    const float* in_w   = (const float*)d_in[1];
    const float* in_b   = (const float*)d_in[2];
    const float* conv_w = (const float*)d_in[3];
    const float* conv_b = (const float*)d_in[4];
    const float* gate_w = (const float*)d_in[5];
    const float* gate_b = (const float*)d_in[6];
    const float* res_w  = (const float*)d_in[7];
    const float* res_b  = (const float*)d_in[8];
    const float* skip_w = (const float*)d_in[9];
    const float* skip_b = (const float*)d_in[10];
    const float* s1_w   = (const float*)d_in[11];
    const float* s1_b   = (const float*)d_in[12];
    const float* s2_w   = (const float*)d_in[13];
    const float* s2_b   = (const float*)d_in[14];
    float* out = (float*)d_out;

    float* hbase = nullptr;
    float* skp   = nullptr;
    cudaGetSymbolAddress((void**)&hbase, g_h);
    cudaGetSymbolAddress((void**)&skp, g_skip);

    k_input<<<NPOS/256, 256>>>(x, in_w, in_b, hbase);

    int cur = 0;
    for (int i = 0; i < NLAYERS; i++) {
        int dd = 1 << (i % 10);
        const float* hin = hbase + (size_t)cur * RC * NPOS;
        float* hout      = hbase + (size_t)(cur ^ 1) * RC * NPOS;
        k_layer<<<LGRID, 256>>>(hin, hout, skp,
                                conv_w + (size_t)i * RC * RC * 2, conv_b + i * RC,
                                gate_w + (size_t)i * RC * RC * 2, gate_b + i * RC,
                                res_w  + (size_t)i * RC * RC,     res_b  + i * RC,
                                skip_w + (size_t)i * RC * RC,     skip_b + i * RC,
                                dd, (i == 0) ? 1 : 0);
        cur ^= 1;
    }

    k_final<<<NPOS/256, 256>>>(skp, s1_w, s1_b, s2_w, s2_b, out);
}

// round 5
// speedup vs baseline: 1.5392x; 1.0104x over previous
#include <cuda_runtime.h>
#include <math.h>

#define BATCH   8
#define TLEN    16384
#define NPOS    (BATCH*TLEN)     // 131072
#define RC      32
#define CIN     256
#define COUT    256
#define NLAYERS 40
#define TILE    128
#define LGRID   (NPOS/TILE)      // 1024

typedef unsigned long long u64;

__device__ float g_h[2][RC * NPOS];
__device__ float g_skip[RC * NPOS];

__device__ __forceinline__ u64 pack2(float lo, float hi) {
    u64 r; asm("mov.b64 %0, {%1, %2};" : "=l"(r) : "f"(lo), "f"(hi)); return r;
}
__device__ __forceinline__ u64 dup2(float x) {
    u64 r; asm("mov.b64 %0, {%1, %1};" : "=l"(r) : "f"(x)); return r;
}
__device__ __forceinline__ void unpack2(u64 v, float& lo, float& hi) {
    asm("mov.b64 {%0, %1}, %2;" : "=f"(lo), "=f"(hi) : "l"(v));
}
// d = a * b + d, packed f32x2 (exact IEEE fp32 per lane)
#define FFMA2(d, a, b) asm("fma.rn.f32x2 %0, %1, %2, %0;" : "+l"(d) : "l"(a), "l"(b))

__device__ __forceinline__ float htanh(float x) {
    float y; asm("tanh.approx.f32 %0, %1;" : "=f"(y) : "f"(x)); return y;
}
// a = tanh(c) * sigmoid(g) = 0.5*tanh(c)*(1 + tanh(0.5*g))
__device__ __forceinline__ float gated(float c, float g) {
    float t1 = htanh(c);
    float t2 = htanh(0.5f * g);
    float ht = 0.5f * t1;
    return fmaf(ht, t2, ht);
}

// ---------------------------------------------------------------------------
// Input 1x1 conv
// ---------------------------------------------------------------------------
__global__ __launch_bounds__(256) void k_input(
    const float* __restrict__ x, const float* __restrict__ w,
    const float* __restrict__ b, float* __restrict__ hout)
{
    __shared__ float ws[CIN][RC];
    __shared__ float bs[RC];
    int tid = threadIdx.x;
    for (int idx = tid; idx < CIN * RC; idx += 256) {
        int o = idx / CIN, ic = idx % CIN;
        ws[ic][o] = w[idx];
    }
    if (tid < RC) bs[tid] = b[tid];
    __syncthreads();

    int p  = blockIdx.x * 256 + tid;
    int bb = p >> 14;
    int t  = p & (TLEN - 1);
    const float* xp = x + ((size_t)bb * CIN) * TLEN + t;

    u64 acc[16];
#pragma unroll
    for (int q = 0; q < 16; q++) acc[q] = pack2(bs[2*q], bs[2*q+1]);

#pragma unroll 4
    for (int ic = 0; ic < CIN; ic++) {
        float xv = __ldg(xp + (size_t)ic * TLEN);
        u64 xd = dup2(xv);
        const ulonglong2* wp = (const ulonglong2*)ws[ic];
#pragma unroll
        for (int q = 0; q < 8; q++) {
            ulonglong2 wv = wp[q];
            FFMA2(acc[2*q],   wv.x, xd);
            FFMA2(acc[2*q+1], wv.y, xd);
        }
    }
#pragma unroll
    for (int q = 0; q < 16; q++) {
        float v0, v1;
        unpack2(acc[q], v0, v1);
        hout[(size_t)(2*q)   * NPOS + p] = v0;
        hout[(size_t)(2*q+1) * NPOS + p] = v1;
    }
}

// ---------------------------------------------------------------------------
// One residual layer. 8 warps, tile=128. Warp -> 4 out chans, lane -> 4 pos.
// ---------------------------------------------------------------------------
__global__ __launch_bounds__(256, 4) void k_layer(
    const float* __restrict__ hin, float* __restrict__ hout,
    float* __restrict__ skip,
    const float* __restrict__ cw, const float* __restrict__ cb,
    const float* __restrict__ gw, const float* __restrict__ gb,
    const float* __restrict__ rw, const float* __restrict__ rb,
    const float* __restrict__ sw, const float* __restrict__ sb,
    int d, int first)
{
    __shared__ float  sh_cur[RC][TILE];   // 16KB
    __shared__ float  sh_pa[RC][TILE];    // 16KB (prev tile, then 'a' tile)
    __shared__ float  swq2[RC][4][RC];    // 16KB [i][kind][o]
    __shared__ float2 swrs2[RC][RC];      //  8KB [i][o] = {rw, sw}

    int tid  = threadIdx.x;
    int base = blockIdx.x * TILE;
    int t0   = base & (TLEN - 1);

    // Weights first so LDG latency overlaps tile staging
    for (int k = tid; k < RC * RC; k += 256) {
        int i = k >> 5, o = k & 31;
        int idx = o * RC + i;
        swq2[i][0][o] = cw[2*idx];
        swq2[i][1][o] = cw[2*idx+1];
        swq2[i][2][o] = gw[2*idx];
        swq2[i][3][o] = gw[2*idx+1];
        swrs2[i][o] = make_float2(rw[idx], sw[idx]);
    }
#pragma unroll
    for (int k = tid; k < RC * (TILE/4); k += 256) {
        int row = k >> 5, c4 = k & 31;
        ((float4*)sh_cur[row])[c4] =
            ((const float4*)(hin + (size_t)row * NPOS + base))[c4];
    }
    if (d >= 4) {
#pragma unroll
        for (int k = tid; k < RC * (TILE/4); k += 256) {
            int row = k >> 5, c4 = k & 31;
            int j = c4 * 4;
            float4 v = make_float4(0.f, 0.f, 0.f, 0.f);
            if (t0 + j >= d)
                v = *(const float4*)(hin + (size_t)row * NPOS + base + j - d);
            ((float4*)sh_pa[row])[c4] = v;
        }
    } else {
        for (int k = tid; k < RC * TILE; k += 256) {
            int row = k >> 7, j = k & 127;
            float v = 0.0f;
            if (t0 + j >= d) v = hin[(size_t)row * NPOS + base + j - d];
            sh_pa[row][j] = v;
        }
    }
    __syncthreads();

    int wid = tid >> 5, l = tid & 31;
    int ow0 = wid * 4;
    int j0  = l * 4;

    // ---- Phase 1: conv + gate ----
    u64 c01[4], c23[4], g01[4], g23[4];
    {
        float4 cbv = *(const float4*)(cb + ow0);
        float4 gbv = *(const float4*)(gb + ow0);
        u64 cA = pack2(cbv.x, cbv.y), cB = pack2(cbv.z, cbv.w);
        u64 gA = pack2(gbv.x, gbv.y), gB = pack2(gbv.z, gbv.w);
#pragma unroll
        for (int p = 0; p < 4; p++) { c01[p]=cA; c23[p]=cB; g01[p]=gA; g23[p]=gB; }
    }

#pragma unroll 4
    for (int i = 0; i < RC; i++) {
        float4 xc4 = *(const float4*)&sh_cur[i][j0];
        float4 xp4 = *(const float4*)&sh_pa[i][j0];
        ulonglong2 wc0 = *(const ulonglong2*)&swq2[i][0][ow0];
        ulonglong2 wc1 = *(const ulonglong2*)&swq2[i][1][ow0];
        ulonglong2 wg0 = *(const ulonglong2*)&swq2[i][2][ow0];
        ulonglong2 wg1 = *(const ulonglong2*)&swq2[i][3][ow0];
        u64 xpd[4] = { dup2(xp4.x), dup2(xp4.y), dup2(xp4.z), dup2(xp4.w) };
        u64 xcd[4] = { dup2(xc4.x), dup2(xc4.y), dup2(xc4.z), dup2(xc4.w) };
#pragma unroll
        for (int p = 0; p < 4; p++) {
            FFMA2(c01[p], wc0.x, xpd[p]);
            FFMA2(c01[p], wc1.x, xcd[p]);
            FFMA2(c23[p], wc0.y, xpd[p]);
            FFMA2(c23[p], wc1.y, xcd[p]);
            FFMA2(g01[p], wg0.x, xpd[p]);
            FFMA2(g01[p], wg1.x, xcd[p]);
            FFMA2(g23[p], wg0.y, xpd[p]);
            FFMA2(g23[p], wg1.y, xcd[p]);
        }
    }

    // ---- Gated activation (MUFU.TANH) ----
    float av[4][4];
#pragma unroll
    for (int p = 0; p < 4; p++) {
        float c0,c1,c2,c3,g0,g1,g2,g3;
        unpack2(c01[p], c0, c1); unpack2(c23[p], c2, c3);
        unpack2(g01[p], g0, g1); unpack2(g23[p], g2, g3);
        av[0][p] = gated(c0, g0);
        av[1][p] = gated(c1, g1);
        av[2][p] = gated(c2, g2);
        av[3][p] = gated(c3, g3);
    }

    __syncthreads();
#pragma unroll
    for (int oo = 0; oo < 4; oo++)
        *(float4*)&sh_pa[ow0 + oo][j0] =
            make_float4(av[oo][0], av[oo][1], av[oo][2], av[oo][3]);
    __syncthreads();

    // ---- Phase 2: res + skip ----
    u64 rs[4][4];
    {
        float4 rbv = *(const float4*)(rb + ow0);
        float4 sbv = *(const float4*)(sb + ow0);
        u64 b0 = pack2(rbv.x, sbv.x), b1 = pack2(rbv.y, sbv.y);
        u64 b2 = pack2(rbv.z, sbv.z), b3 = pack2(rbv.w, sbv.w);
#pragma unroll
        for (int p = 0; p < 4; p++) { rs[0][p]=b0; rs[1][p]=b1; rs[2][p]=b2; rs[3][p]=b3; }
    }

#pragma unroll 4
    for (int i = 0; i < RC; i++) {
        float4 a4 = *(const float4*)&sh_pa[i][j0];
        ulonglong2 w01 = *(const ulonglong2*)&swrs2[i][ow0];
        ulonglong2 w23 = *(const ulonglong2*)&swrs2[i][ow0 + 2];
        u64 ad[4] = { dup2(a4.x), dup2(a4.y), dup2(a4.z), dup2(a4.w) };
#pragma unroll
        for (int p = 0; p < 4; p++) {
            FFMA2(rs[0][p], w01.x, ad[p]);
            FFMA2(rs[1][p], w01.y, ad[p]);
            FFMA2(rs[2][p], w23.x, ad[p]);
            FFMA2(rs[3][p], w23.y, ad[p]);
        }
    }

    // ---- Writeback ----
#pragma unroll
    for (int oo = 0; oo < 4; oo++) {
        size_t idx = (size_t)(ow0 + oo) * NPOS + base + j0;
        float4 xc = *(const float4*)&sh_cur[ow0 + oo][j0];
        float rv0,sv0,rv1,sv1,rv2,sv2,rv3,sv3;
        unpack2(rs[oo][0], rv0, sv0);
        unpack2(rs[oo][1], rv1, sv1);
        unpack2(rs[oo][2], rv2, sv2);
        unpack2(rs[oo][3], rv3, sv3);
        float4 ho = make_float4(xc.x + rv0, xc.y + rv1, xc.z + rv2, xc.w + rv3);
        *(float4*)&hout[idx] = ho;
        float4 sv = make_float4(sv0, sv1, sv2, sv3);
        if (!first) {
            float4 old = *(const float4*)&skip[idx];
            sv.x += old.x; sv.y += old.y; sv.z += old.z; sv.w += old.w;
        }
        *(float4*)&skip[idx] = sv;
    }
}

// ---------------------------------------------------------------------------
// Output head
// ---------------------------------------------------------------------------
__global__ __launch_bounds__(256) void k_final(
    const float* __restrict__ skip,
    const float* __restrict__ w1, const float* __restrict__ b1,
    const float* __restrict__ w2, const float* __restrict__ b2,
    float* __restrict__ out)
{
    __shared__ float ws1[RC * RC];
    __shared__ float ws2t[RC][COUT];
    __shared__ float bs1[RC];
    __shared__ float bs2[COUT];
    int tid = threadIdx.x;
    for (int idx = tid; idx < RC * RC; idx += 256) ws1[idx] = w1[idx];
    for (int idx = tid; idx < COUT * RC; idx += 256) {
        int o = idx / RC, i = idx % RC;
        ws2t[i][o] = w2[idx];
    }
    if (tid < RC) bs1[tid] = b1[tid];
    if (tid < COUT) bs2[tid] = b2[tid];
    __syncthreads();

    int p  = blockIdx.x * 256 + tid;
    int bb = p >> 14;
    int t  = p & (TLEN - 1);

    float sk[RC];
#pragma unroll
    for (int i = 0; i < RC; i++) sk[i] = skip[(size_t)i * NPOS + p];

    float u[RC];
#pragma unroll
    for (int o = 0; o < RC; o++) {
        float acc = bs1[o];
#pragma unroll
        for (int i = 0; i < RC; i++) acc = fmaf(ws1[o * RC + i], sk[i], acc);
        u[o] = fmaxf(acc, 0.0f);
    }

    float* op = out + ((size_t)bb * COUT) * TLEN + t;
    for (int og = 0; og < COUT / 16; og++) {
        int o0 = og * 16;
        u64 acc[8];
#pragma unroll
        for (int q = 0; q < 8; q++) acc[q] = pack2(bs2[o0 + 2*q], bs2[o0 + 2*q + 1]);
#pragma unroll 8
        for (int i = 0; i < RC; i++) {
            u64 ud = dup2(u[i]);
            const ulonglong2* wp = (const ulonglong2*)&ws2t[i][o0];
#pragma unroll
            for (int q2 = 0; q2 < 4; q2++) {
                ulonglong2 wv = wp[q2];
                FFMA2(acc[2*q2],   wv.x, ud);
                FFMA2(acc[2*q2+1], wv.y, ud);
            }
        }
#pragma unroll
        for (int q = 0; q < 8; q++) {
            float v0, v1;
            unpack2(acc[q], v0, v1);
            op[(size_t)(o0 + 2*q)     * TLEN] = v0;
            op[(size_t)(o0 + 2*q + 1) * TLEN] = v1;
        }
    }
}

// ---------------------------------------------------------------------------
extern "C" void kernel_launch(void* const* d_in, const int* in_sizes, int n_in,
                              void* d_out, int out_size)
{
    const float* x      = (const float*)d_in[0];
    const float* in_w   = (const float*)d_in[1];
    const float* in_b   = (const float*)d_in[2];
    const float* conv_w = (const float*)d_in[3];
    const float* conv_b = (const float*)d_in[4];
    const float* gate_w = (const float*)d_in[5];
    const float* gate_b = (const float*)d_in[6];
    const float* res_w  = (const float*)d_in[7];
    const float* res_b  = (const float*)d_in[8];
    const float* skip_w = (const float*)d_in[9];
    const float* skip_b = (const float*)d_in[10];
    const float* s1_w   = (const float*)d_in[11];
    const float* s1_b   = (const float*)d_in[12];
    const float* s2_w   = (const float*)d_in[13];
    const float* s2_b   = (const float*)d_in[14];
    float* out = (float*)d_out;

    float* hbase = nullptr;
    float* skp   = nullptr;
    cudaGetSymbolAddress((void**)&hbase, g_h);
    cudaGetSymbolAddress((void**)&skp, g_skip);

    k_input<<<NPOS/256, 256>>>(x, in_w, in_b, hbase);

    int cur = 0;
    for (int i = 0; i < NLAYERS; i++) {
        int dd = 1 << (i % 10);
        const float* hin = hbase + (size_t)cur * RC * NPOS;
        float* hout      = hbase + (size_t)(cur ^ 1) * RC * NPOS;
        k_layer<<<LGRID, 256>>>(hin, hout, skp,
                                conv_w + (size_t)i * RC * RC * 2, conv_b + i * RC,
                                gate_w + (size_t)i * RC * RC * 2, gate_b + i * RC,
                                res_w  + (size_t)i * RC * RC,     res_b  + i * RC,
                                skip_w + (size_t)i * RC * RC,     skip_b + i * RC,
                                dd, (i == 0) ? 1 : 0);
        cur ^= 1;
    }

    k_final<<<NPOS/256, 256>>>(skp, s1_w, s1_b, s2_w, s2_b, out);
}